// round 3
// baseline (speedup 1.0000x reference)
#include <cuda_runtime.h>
#include <math.h>

#define NJ     23
#define NP     16
#define NPAIR  8
#define VTOT   500000
#define V3     (VTOT * 3)
#define OUT_JOFF (NP * V3)

struct Ptrs { const float* p[11]; };

// Pose-pair-interleaved skinning matrices: g_A2[(j*8+pair)*12 + a*4+b]
//   .x = pose 2*pair, .y = pose 2*pair+1 ; e = a*4+b, b==3 is translation.
__device__ float2 g_A2[NJ * NPAIR * 12];
__device__ float2 g_shift2[NPAIR * 3];

// ---------------------------------------------------------------------------
// Kernel 1: tiny — pose -> Rodrigues -> kinematic chain -> A, shift, joints out
// ---------------------------------------------------------------------------
__global__ void lbs_prep(const float* __restrict__ joints,
                         const float* __restrict__ disp,
                         const float* __restrict__ rnd,
                         Ptrs pp, float* __restrict__ out)
{
    int p = threadIdx.x;
    if (p >= NP) return;

    const int PAR[NJ] = {-1,0,1,1,3,4,5,4,7,4,9,1,11,12,13,12,15,12,17,0,19,0,21};
    const int SLOT[11] = {0,3,4,5,7,9,11,12,13,15,17};
    const float HALFPI = 1.5707963267948966f, QUART = 0.7853981633974483f;
    const float SC[11] = {QUART,HALFPI,HALFPI,QUART,QUART,QUART,
                          HALFPI,HALFPI,QUART,QUART,QUART};

    float pose[NJ][3];
    for (int j = 0; j < NJ; j++) { pose[j][0]=0.f; pose[j][1]=0.f; pose[j][2]=0.f; }
    for (int s = 0; s < 11; s++) {
        const float* prm = pp.p[s] + p * 3;
        pose[SLOT[s]][0] = SC[s] * tanhf(prm[0]);
        pose[SLOT[s]][1] = SC[s] * tanhf(prm[1]);
        pose[SLOT[s]][2] = SC[s] * tanhf(prm[2]);
    }

    float Gr[NJ][9], Gt[NJ][3];
    for (int j = 0; j < NJ; j++) {
        float rx = pose[j][0], ry = pose[j][1], rz = pose[j][2];
        float ang = sqrtf(rx*rx + ry*ry + rz*rz + 1e-16f);
        float ax = rx / ang, ay = ry / ang, az = rz / ang;
        float s = sinf(ang), c = cosf(ang), t = 1.0f - c;
        float R[9];
        R[0] = 1.0f - t*(ay*ay + az*az); R[1] = -s*az + t*ax*ay; R[2] =  s*ay + t*ax*az;
        R[3] =  s*az + t*ax*ay; R[4] = 1.0f - t*(ax*ax + az*az); R[5] = -s*ax + t*ay*az;
        R[6] = -s*ay + t*ax*az; R[7] =  s*ax + t*ay*az; R[8] = 1.0f - t*(ax*ax + ay*ay);

        float rel[3];
        if (j == 0) {
            rel[0] = joints[0]; rel[1] = joints[1]; rel[2] = joints[2];
        } else {
            int q = PAR[j];
            rel[0] = joints[j*3+0] - joints[q*3+0];
            rel[1] = joints[j*3+1] - joints[q*3+1];
            rel[2] = joints[j*3+2] - joints[q*3+2];
        }
        if (j == 0) {
            for (int e = 0; e < 9; e++) Gr[0][e] = R[e];
            Gt[0][0] = rel[0]; Gt[0][1] = rel[1]; Gt[0][2] = rel[2];
        } else {
            int q = PAR[j];
            for (int a = 0; a < 3; a++)
                for (int b = 0; b < 3; b++)
                    Gr[j][a*3+b] = Gr[q][a*3+0]*R[0*3+b]
                                 + Gr[q][a*3+1]*R[1*3+b]
                                 + Gr[q][a*3+2]*R[2*3+b];
            for (int a = 0; a < 3; a++)
                Gt[j][a] = Gr[q][a*3+0]*rel[0] + Gr[q][a*3+1]*rel[1]
                         + Gr[q][a*3+2]*rel[2] + Gt[q][a];
        }
    }

    float sh[3];
    for (int k = 0; k < 3; k++)
        sh[k] = rnd[p*3+k] + 3.0f * tanhf(disp[p*3+k]);

    // posed joints + shift
    for (int j = 0; j < NJ; j++)
        for (int k = 0; k < 3; k++)
            out[OUT_JOFF + (p*NJ + j)*3 + k] = Gt[j][k] + sh[k];

    // A = [G_rot | G_t - G_rot * j_orig], pose-pair interleaved
    int pair = p >> 1, lane = p & 1;
    for (int j = 0; j < NJ; j++) {
        float jx = joints[j*3], jy = joints[j*3+1], jz = joints[j*3+2];
        float* dst = (float*)&g_A2[(j*NPAIR + pair)*12];
        for (int a = 0; a < 3; a++) {
            float At = Gt[j][a] - (Gr[j][a*3]*jx + Gr[j][a*3+1]*jy + Gr[j][a*3+2]*jz);
            dst[(a*4+0)*2 + lane] = Gr[j][a*3+0];
            dst[(a*4+1)*2 + lane] = Gr[j][a*3+1];
            dst[(a*4+2)*2 + lane] = Gr[j][a*3+2];
            dst[(a*4+3)*2 + lane] = At;
        }
    }
    ((float*)&g_shift2[pair*3+0])[lane] = sh[0];
    ((float*)&g_shift2[pair*3+1])[lane] = sh[1];
    ((float*)&g_shift2[pair*3+2])[lane] = sh[2];
}

// ---------------------------------------------------------------------------
// Packed f32x2 FMA (sm_103a FFMA2 — ptxas won't auto-fuse from C++)
// ---------------------------------------------------------------------------
union F2U { float2 f; unsigned long long u; };

__device__ __forceinline__ float2 ffma2(float2 a, float2 b, float2 c)
{
    F2U A, B, C, D;
    A.f = a; B.f = b; C.f = c;
    asm("fma.rn.f32x2 %0, %1, %2, %3;"
        : "=l"(D.u) : "l"(A.u), "l"(B.u), "l"(C.u));
    return D.f;
}

// ---------------------------------------------------------------------------
// Kernel 2: the big one. Block = 256 vertices (128 threads x 2 vertices),
// each thread accumulates all 16 poses (8 f32x2 pose-pairs).
// ---------------------------------------------------------------------------
__global__ void __launch_bounds__(128, 2)
lbs_main(const float* __restrict__ verts,
         const float* __restrict__ W,
         float* __restrict__ out)
{
    __shared__ __align__(16) float2 sA[NJ * NPAIR * 12];   // 17664 B
    __shared__ __align__(16) float  sW[256 * NJ];          // 23552 B
    __shared__ float2 sSh[NPAIR * 3];

    const int tid = threadIdx.x;
    const int base = blockIdx.x * 256;

    // Stage A (broadcast matrix) via float4
    {
        float4* d = (float4*)sA;
        const float4* s = (const float4*)g_A2;
        #pragma unroll
        for (int i = tid; i < (NJ * NPAIR * 12) / 2; i += 128) d[i] = s[i];
    }
    if (tid < NPAIR * 3) sSh[tid] = g_shift2[tid];

    // Stage this block's weight rows (region is 16B-aligned: 256*23*4 % 16 == 0)
    {
        int nv  = min(256, VTOT - base);
        int nf4 = (nv * NJ) / 4;     // 1472 (full) or 184 (tail) — both exact
        float4* d = (float4*)sW;
        const float4* s = (const float4*)(W + (long long)base * NJ);
        for (int i = tid; i < nf4; i += 128) d[i] = s[i];
    }
    __syncthreads();

    const int vA = base + tid;
    const int vB = vA + 128;
    const bool okA = vA < VTOT;
    const bool okB = vB < VTOT;

    float ax_ = 0.f, ay_ = 0.f, az_ = 0.f, bx_ = 0.f, by_ = 0.f, bz_ = 0.f;
    if (okA) { ax_ = verts[vA*3+0]; ay_ = verts[vA*3+1]; az_ = verts[vA*3+2]; }
    if (okB) { bx_ = verts[vB*3+0]; by_ = verts[vB*3+1]; bz_ = verts[vB*3+2]; }
    const float2 xA = make_float2(ax_, ax_), yA = make_float2(ay_, ay_), zA = make_float2(az_, az_);
    const float2 xB = make_float2(bx_, bx_), yB = make_float2(by_, by_), zB = make_float2(bz_, bz_);

    float2 accA[NPAIR][3], accB[NPAIR][3];
    #pragma unroll
    for (int pr = 0; pr < NPAIR; pr++)
        #pragma unroll
        for (int a = 0; a < 3; a++) {
            accA[pr][a] = make_float2(0.f, 0.f);
            accB[pr][a] = make_float2(0.f, 0.f);
        }

    for (int j = 0; j < NJ; ++j) {
        const float wa = sW[tid * NJ + j];
        const float wb = sW[(tid + 128) * NJ + j];
        const float2 wA2 = make_float2(wa, wa);
        const float2 wB2 = make_float2(wb, wb);
        const float4* Aj = (const float4*)(sA + j * NPAIR * 12);

        #pragma unroll
        for (int pr = 0; pr < NPAIR; pr++) {
            const float4 q0 = Aj[pr*6+0], q1 = Aj[pr*6+1], q2 = Aj[pr*6+2];
            const float4 q3 = Aj[pr*6+3], q4 = Aj[pr*6+4], q5 = Aj[pr*6+5];
            const float2 m00 = make_float2(q0.x,q0.y), m01 = make_float2(q0.z,q0.w);
            const float2 m02 = make_float2(q1.x,q1.y), m03 = make_float2(q1.z,q1.w);
            const float2 m10 = make_float2(q2.x,q2.y), m11 = make_float2(q2.z,q2.w);
            const float2 m12 = make_float2(q3.x,q3.y), m13 = make_float2(q3.z,q3.w);
            const float2 m20 = make_float2(q4.x,q4.y), m21 = make_float2(q4.z,q4.w);
            const float2 m22 = make_float2(q5.x,q5.y), m23 = make_float2(q5.z,q5.w);

            float2 t;
            t = ffma2(m00, xA, ffma2(m01, yA, ffma2(m02, zA, m03)));
            accA[pr][0] = ffma2(wA2, t, accA[pr][0]);
            t = ffma2(m10, xA, ffma2(m11, yA, ffma2(m12, zA, m13)));
            accA[pr][1] = ffma2(wA2, t, accA[pr][1]);
            t = ffma2(m20, xA, ffma2(m21, yA, ffma2(m22, zA, m23)));
            accA[pr][2] = ffma2(wA2, t, accA[pr][2]);

            t = ffma2(m00, xB, ffma2(m01, yB, ffma2(m02, zB, m03)));
            accB[pr][0] = ffma2(wB2, t, accB[pr][0]);
            t = ffma2(m10, xB, ffma2(m11, yB, ffma2(m12, zB, m13)));
            accB[pr][1] = ffma2(wB2, t, accB[pr][1]);
            t = ffma2(m20, xB, ffma2(m21, yB, ffma2(m22, zB, m23)));
            accB[pr][2] = ffma2(wB2, t, accB[pr][2]);
        }
    }

    // Epilogue: add shift, scatter to out[p][v][a]
    #pragma unroll
    for (int pr = 0; pr < NPAIR; pr++) {
        const int p0 = 2 * pr, p1 = 2 * pr + 1;
        #pragma unroll
        for (int a = 0; a < 3; a++) {
            const float2 s = sSh[pr * 3 + a];
            if (okA) {
                out[p0 * V3 + vA * 3 + a] = accA[pr][a].x + s.x;
                out[p1 * V3 + vA * 3 + a] = accA[pr][a].y + s.y;
            }
            if (okB) {
                out[p0 * V3 + vB * 3 + a] = accB[pr][a].x + s.x;
                out[p1 * V3 + vB * 3 + a] = accB[pr][a].y + s.y;
            }
        }
    }
}

// ---------------------------------------------------------------------------
extern "C" void kernel_launch(void* const* d_in, const int* in_sizes, int n_in,
                              void* d_out, int out_size)
{
    const float* vertices = (const float*)d_in[0];
    const float* joints   = (const float*)d_in[1];
    const float* weights  = (const float*)d_in[2];
    const float* disp     = (const float*)d_in[3];
    const float* rnd      = (const float*)d_in[4];
    Ptrs pp;
    for (int i = 0; i < 11; i++) pp.p[i] = (const float*)d_in[5 + i];
    float* out = (float*)d_out;

    lbs_prep<<<1, 32>>>(joints, disp, rnd, pp, out);

    const int nblocks = (VTOT + 255) / 256;   // 1954
    lbs_main<<<nblocks, 128>>>(vertices, weights, out);
}